// round 1
// baseline (speedup 1.0000x reference)
#include <cuda_runtime.h>

#define NUSER 100000
#define NITEM 50000
#define NN    150000
#define EE    2400000
#define F     64
#define Q     4096
#define NEG_SLOPE 0.2f

// ---------------- device scratch (no allocs allowed) ----------------
__device__ __align__(16) float g_x[NN * F];     // current node features
__device__ __align__(16) float g_h[NN * F];     // h = x @ W
__device__ float g_as[NN];
__device__ float g_ad[NN];
__device__ int   g_rowptr[NN + 1];
__device__ int   g_fill[NN];                    // counts, then running offsets
__device__ int   g_col[EE];                     // CSR col (src), grouped by dst
__device__ __align__(16) float g_uo[Q * F];     // online user rows
__device__ __align__(16) float g_io[Q * F];     // online item rows

__device__ __forceinline__ float lrelu(float v) {
    // v>=0 -> v ; v<0 -> 0.2v == max(v, 0.2v)
    return fmaxf(v, NEG_SLOPE * v);
}

// ---------------- CSR build ----------------
__global__ void zero_counts_kernel() {
    int i = blockIdx.x * blockDim.x + threadIdx.x;
    if (i < NN) g_fill[i] = 0;
}

__global__ void hist_kernel(const int* __restrict__ ei) {
    int i = blockIdx.x * blockDim.x + threadIdx.x;
    if (i < EE) atomicAdd(&g_fill[ei[EE + i]], 1);
}

__global__ void scan_kernel() {
    __shared__ int sb[1024];
    int t = threadIdx.x;
    const int CH = 147;                 // 1024*147 = 150528 >= NN
    int start = t * CH;
    int end = min(start + CH, NN);
    int s = 0;
    for (int i = start; i < end; i++) s += g_fill[i];
    sb[t] = s;
    __syncthreads();
    for (int o = 1; o < 1024; o <<= 1) {
        int v = 0;
        if (t >= o) v = sb[t - o];
        __syncthreads();
        if (t >= o) sb[t] += v;
        __syncthreads();
    }
    int run = (t == 0) ? 0 : sb[t - 1];
    for (int i = start; i < end; i++) {
        int cnt = g_fill[i];
        g_rowptr[i] = run;
        g_fill[i]   = run;
        run += cnt;
    }
    if (t == 1023) g_rowptr[NN] = sb[1023];
}

__global__ void scatter_kernel(const int* __restrict__ ei) {
    int i = blockIdx.x * blockDim.x + threadIdx.x;
    if (i < EE) {
        int d = ei[EE + i];
        int pos = atomicAdd(&g_fill[d], 1);
        g_col[pos] = ei[i];
    }
}

// ---------------- encoder kernels ----------------
__global__ void concat_kernel(const float4* __restrict__ ue, const float4* __restrict__ ie) {
    int i = blockIdx.x * blockDim.x + threadIdx.x;   // over NN*16 float4
    const int UQ = NUSER * (F / 4);
    if (i < UQ) ((float4*)g_x)[i] = ue[i];
    else if (i < NN * (F / 4)) ((float4*)g_x)[i] = ie[i - UQ];
}

// g_h = g_x @ W  (W: [64,64] row-major, h[r][c] = sum_k x[r][k]*W[k][c])
__global__ void __launch_bounds__(256) gemm64_kernel(const float* __restrict__ W) {
    __shared__ float Xs[64 * 64];
    int tid = threadIdx.x;
    int r0  = blockIdx.x * 64;
    int c   = tid & 63;
    int rb  = (tid >> 6) * 16;

    float Wc[64];
#pragma unroll
    for (int k = 0; k < 64; k++) Wc[k] = W[k * 64 + c];

    const float4* X4  = (const float4*)(g_x + (size_t)r0 * F);
    float4*       Xs4 = (float4*)Xs;
#pragma unroll
    for (int i = 0; i < 4; i++) {
        int idx = tid + i * 256;       // float4 index in tile (0..1023)
        int row = idx >> 4;
        float4 v = make_float4(0.f, 0.f, 0.f, 0.f);
        if (r0 + row < NN) v = X4[idx];
        Xs4[idx] = v;
    }
    __syncthreads();

    float acc[16];
#pragma unroll
    for (int i = 0; i < 16; i++) acc[i] = 0.f;

#pragma unroll
    for (int kq = 0; kq < 16; kq++) {
#pragma unroll
        for (int i = 0; i < 16; i++) {
            float4 x4 = Xs4[(rb + i) * 16 + kq];
            acc[i] = fmaf(x4.x, Wc[4 * kq + 0], acc[i]);
            acc[i] = fmaf(x4.y, Wc[4 * kq + 1], acc[i]);
            acc[i] = fmaf(x4.z, Wc[4 * kq + 2], acc[i]);
            acc[i] = fmaf(x4.w, Wc[4 * kq + 3], acc[i]);
        }
    }
#pragma unroll
    for (int i = 0; i < 16; i++) {
        int r = r0 + rb + i;
        if (r < NN) g_h[(size_t)r * F + c] = acc[i];
    }
}

// as[n] = h[n]·a_src, ad[n] = h[n]·a_dst  (one warp per node)
__global__ void dots_kernel(const float* __restrict__ asrc, const float* __restrict__ adst) {
    int w = (blockIdx.x * blockDim.x + threadIdx.x) >> 5;
    int lane = threadIdx.x & 31;
    if (w >= NN) return;
    float h0 = g_h[(size_t)w * F + lane];
    float h1 = g_h[(size_t)w * F + 32 + lane];
    float s = h0 * asrc[lane] + h1 * asrc[32 + lane];
    float d = h0 * adst[lane] + h1 * adst[32 + lane];
#pragma unroll
    for (int o = 16; o; o >>= 1) {
        s += __shfl_xor_sync(0xffffffffu, s, o);
        d += __shfl_xor_sync(0xffffffffu, d, o);
    }
    if (lane == 0) { g_as[w] = s; g_ad[w] = d; }
}

// One warp per destination node: online GAT softmax-aggregate (incl. self loop).
__global__ void __launch_bounds__(256) agg_kernel(const float* __restrict__ bias) {
    int d = (blockIdx.x * blockDim.x + threadIdx.x) >> 5;
    int lane = threadIdx.x & 31;
    if (d >= NN) return;

    int s0 = g_rowptr[d];
    int s1 = g_rowptr[d + 1];
    float adv   = g_ad[d];
    float eself = lrelu(g_as[d] + adv);

    // pass 1: max
    float m = eself;
    for (int k = s0 + lane; k < s1; k += 32) {
        int s = g_col[k];
        m = fmaxf(m, lrelu(g_as[s] + adv));
    }
#pragma unroll
    for (int o = 16; o; o >>= 1) m = fmaxf(m, __shfl_xor_sync(0xffffffffu, m, o));

    // pass 2: exp weights + weighted sum of h[src]
    const float2* h2 = (const float2*)g_h;
    float wself = __expf(eself - m);
    float2 hd = h2[(size_t)d * 32 + lane];
    float acc0 = wself * hd.x;
    float acc1 = wself * hd.y;
    float den_l = 0.f;

    for (int base = s0; base < s1; base += 32) {
        int k = base + lane;
        int s = 0;
        float w = 0.f;
        if (k < s1) {
            s = g_col[k];
            w = __expf(lrelu(g_as[s] + adv) - m);
            den_l += w;
        }
        int cnt = min(32, s1 - base);
        for (int j = 0; j < cnt; j++) {
            float wj = __shfl_sync(0xffffffffu, w, j);
            int   sj = __shfl_sync(0xffffffffu, s, j);
            float2 hv = h2[(size_t)sj * 32 + lane];
            acc0 = fmaf(wj, hv.x, acc0);
            acc1 = fmaf(wj, hv.y, acc1);
        }
    }
#pragma unroll
    for (int o = 16; o; o >>= 1) den_l += __shfl_xor_sync(0xffffffffu, den_l, o);
    float inv = 1.f / (wself + den_l);

    float2 o2;
    o2.x = acc0 * inv + bias[2 * lane];
    o2.y = acc1 * inv + bias[2 * lane + 1];
    ((float2*)g_x)[(size_t)d * 32 + lane] = o2;
}

// stash online encoder results for the 4096 queried users/items
__global__ void gather_kernel(const int* __restrict__ user, const int* __restrict__ item) {
    int w = (blockIdx.x * blockDim.x + threadIdx.x) >> 5;
    int lane = threadIdx.x & 31;
    const float2* X2 = (const float2*)g_x;
    if (w < Q) {
        ((float2*)g_uo)[(size_t)w * 32 + lane] = X2[(size_t)user[w] * 32 + lane];
    } else if (w < 2 * Q) {
        int q = w - Q;
        ((float2*)g_io)[(size_t)q * 32 + lane] = X2[((size_t)NUSER + item[q]) * 32 + lane];
    }
}

// out = [u_online@predW^T+b | u_target | i_online@predW^T+b | i_target], each [4096,64]
__global__ void final_kernel(const float* __restrict__ pW, const float* __restrict__ pb,
                             const int* __restrict__ user, const int* __restrict__ item,
                             float* __restrict__ out) {
    __shared__ float Ws[64 * 65];
    __shared__ float rows[4 * 64];
    int tid = threadIdx.x;
    bool isU = blockIdx.x < (Q / 4);
    int qb = (isU ? blockIdx.x : blockIdx.x - (Q / 4)) * 4;

    for (int i = tid; i < 4096; i += 256) Ws[(i >> 6) * 65 + (i & 63)] = pW[i];
    const float* src = isU ? g_uo : g_io;
    rows[tid] = src[(size_t)qb * F + tid];
    __syncthreads();

    int qr = tid >> 6, c = tid & 63;
    int q = qb + qr;
    float acc = pb[c];
#pragma unroll
    for (int k = 0; k < 64; k++) acc = fmaf(rows[qr * F + k], Ws[c * 65 + k], acc);

    size_t base = isU ? 0 : (size_t)2 * Q * F;
    out[base + (size_t)q * F + c] = acc;

    int node = isU ? user[q] : (NUSER + item[q]);
    out[base + (size_t)Q * F + (size_t)q * F + c] = g_x[(size_t)node * F + c];
}

// ---------------- host ----------------
extern "C" void kernel_launch(void* const* d_in, const int* in_sizes, int n_in,
                              void* d_out, int out_size) {
    const float *uembo, *iembo, *Wo, *aso, *ado, *bo;
    const float *uembt, *iembt, *Wt, *ast, *adt, *bt;
    const float *pW, *pb;
    const int *user, *item, *ei;

    if (in_sizes[0] == Q) {  // setup_inputs dict order: user,item,edge_index, then params
        user  = (const int*)d_in[0];
        item  = (const int*)d_in[1];
        ei    = (const int*)d_in[2];
        uembo = (const float*)d_in[3];  iembo = (const float*)d_in[4];
        Wo    = (const float*)d_in[5];
        aso   = (const float*)d_in[6];  ado   = (const float*)d_in[7];  bo = (const float*)d_in[8];
        uembt = (const float*)d_in[9];  iembt = (const float*)d_in[10];
        Wt    = (const float*)d_in[11];
        ast   = (const float*)d_in[12]; adt   = (const float*)d_in[13]; bt = (const float*)d_in[14];
        pW    = (const float*)d_in[15]; pb    = (const float*)d_in[16];
    } else {                 // reference signature order
        uembo = (const float*)d_in[0];  iembo = (const float*)d_in[1];
        Wo    = (const float*)d_in[2];
        aso   = (const float*)d_in[3];  ado   = (const float*)d_in[4];  bo = (const float*)d_in[5];
        uembt = (const float*)d_in[6];  iembt = (const float*)d_in[7];
        Wt    = (const float*)d_in[8];
        ast   = (const float*)d_in[9];  adt   = (const float*)d_in[10]; bt = (const float*)d_in[11];
        pW    = (const float*)d_in[12]; pb    = (const float*)d_in[13];
        user  = (const int*)d_in[14];
        item  = (const int*)d_in[15];
        ei    = (const int*)d_in[16];
    }
    float* out = (float*)d_out;

    // build CSR (by destination) for this launch
    zero_counts_kernel<<<(NN + 255) / 256, 256>>>();
    hist_kernel<<<EE / 256, 256>>>(ei);
    scan_kernel<<<1, 1024>>>();
    scatter_kernel<<<EE / 256, 256>>>(ei);

    const int GEMM_BLOCKS = (NN + 63) / 64;     // 2344
    const int WARP_BLOCKS = NN / 8;             // 18750 (150000 warps)

    // --- online encoder ---
    concat_kernel<<<NN * (F / 4) / 256, 256>>>((const float4*)uembo, (const float4*)iembo);
    for (int l = 0; l < 3; l++) {
        gemm64_kernel<<<GEMM_BLOCKS, 256>>>(Wo + (size_t)l * F * F);
        dots_kernel<<<WARP_BLOCKS, 256>>>(aso + l * F, ado + l * F);
        agg_kernel<<<WARP_BLOCKS, 256>>>(bo + l * F);
    }
    gather_kernel<<<(2 * Q) / 8, 256>>>(user, item);

    // --- target encoder ---
    concat_kernel<<<NN * (F / 4) / 256, 256>>>((const float4*)uembt, (const float4*)iembt);
    for (int l = 0; l < 3; l++) {
        gemm64_kernel<<<GEMM_BLOCKS, 256>>>(Wt + (size_t)l * F * F);
        dots_kernel<<<WARP_BLOCKS, 256>>>(ast + l * F, adt + l * F);
        agg_kernel<<<WARP_BLOCKS, 256>>>(bt + l * F);
    }

    final_kernel<<<2 * (Q / 4), 256>>>(pW, pb, user, item, out);
}

// round 3
// speedup vs baseline: 1.1075x; 1.1075x over previous
#include <cuda_runtime.h>

#define NUSER 100000
#define NITEM 50000
#define NN    150000
#define EE    2400000
#define F     64
#define Q     4096
#define NEG_SLOPE 0.2f

// ---------------- device scratch (no allocs allowed) ----------------
__device__ __align__(16) float g_x[2][NN * F];   // [0]=online, [1]=target
__device__ __align__(16) float g_h[2][NN * F];
__device__ __align__(8)  float2 g_as2[NN];       // (as_online, as_target)
__device__ __align__(8)  float2 g_ad2[NN];       // (ad_online, ad_target)
__device__ int g_rowptr[NN + 1];
__device__ int g_fill[NN];
__device__ int g_col[EE];

__device__ __forceinline__ float lrelu(float v) { return fmaxf(v, NEG_SLOPE * v); }

// ---------------- CSR build ----------------
__global__ void zero_counts_kernel() {
    int i = blockIdx.x * blockDim.x + threadIdx.x;
    if (i < NN) g_fill[i] = 0;
}

__global__ void hist_kernel(const int* __restrict__ ei) {
    int i = blockIdx.x * blockDim.x + threadIdx.x;
    if (i < EE) atomicAdd(&g_fill[ei[EE + i]], 1);
}

__global__ void scan_kernel() {
    __shared__ int sb[1024];
    int t = threadIdx.x;
    const int CH = 147;
    int start = t * CH;
    int end = min(start + CH, NN);
    int s = 0;
    for (int i = start; i < end; i++) s += g_fill[i];
    sb[t] = s;
    __syncthreads();
    for (int o = 1; o < 1024; o <<= 1) {
        int v = 0;
        if (t >= o) v = sb[t - o];
        __syncthreads();
        if (t >= o) sb[t] += v;
        __syncthreads();
    }
    int run = (t == 0) ? 0 : sb[t - 1];
    for (int i = start; i < end; i++) {
        int cnt = g_fill[i];
        g_rowptr[i] = run;
        g_fill[i]   = run;
        run += cnt;
    }
    if (t == 1023) g_rowptr[NN] = sb[1023];
}

__global__ void scatter_kernel(const int* __restrict__ ei) {
    int i = blockIdx.x * blockDim.x + threadIdx.x;
    if (i < EE) {
        int d = ei[EE + i];
        int pos = atomicAdd(&g_fill[d], 1);
        g_col[pos] = ei[i];
    }
}

// ---------------- both-encoder concat ----------------
__global__ void concat2_kernel(const float4* __restrict__ ueo, const float4* __restrict__ ieo,
                               const float4* __restrict__ uet, const float4* __restrict__ iet) {
    int i = blockIdx.x * blockDim.x + threadIdx.x;
    const int PER = NN * (F / 4);
    const int UQ  = NUSER * (F / 4);
    if (i >= 2 * PER) return;
    int enc = (i >= PER) ? 1 : 0;
    int j = i - enc * PER;
    float4 v;
    if (j < UQ) v = enc ? uet[j] : ueo[j];
    else        v = enc ? iet[j - UQ] : ieo[j - UQ];
    ((float4*)g_x[enc])[j] = v;
}

// ---------------- gemm (h = x @ W) with fused attention dots ----------------
__global__ void __launch_bounds__(256) gemm_dots_kernel(
    const float* __restrict__ Wo, const float* __restrict__ Wt,
    const float* __restrict__ aso, const float* __restrict__ ado,
    const float* __restrict__ ast, const float* __restrict__ adt) {
    int enc = blockIdx.y;
    const float* W   = enc ? Wt  : Wo;
    const float* avs = enc ? ast : aso;
    const float* avd = enc ? adt : ado;
    const float* X   = g_x[enc];
    float*       H   = g_h[enc];

    __shared__ float Xs[64 * 64];
    int tid = threadIdx.x;
    int r0  = blockIdx.x * 64;
    int c   = tid & 63;
    int rb  = (tid >> 6) * 16;

    float Wc[64];
#pragma unroll
    for (int k = 0; k < 64; k++) Wc[k] = W[k * 64 + c];

    const float4* X4  = (const float4*)(X + (size_t)r0 * F);
    float4*       Xs4 = (float4*)Xs;
#pragma unroll
    for (int i = 0; i < 4; i++) {
        int idx = tid + i * 256;
        int row = idx >> 4;
        float4 v = make_float4(0.f, 0.f, 0.f, 0.f);
        if (r0 + row < NN) v = X4[idx];
        Xs4[idx] = v;
    }
    __syncthreads();

    float acc[16];
#pragma unroll
    for (int i = 0; i < 16; i++) acc[i] = 0.f;

#pragma unroll
    for (int kq = 0; kq < 16; kq++) {
#pragma unroll
        for (int i = 0; i < 16; i++) {
            float4 x4 = Xs4[(rb + i) * 16 + kq];
            acc[i] = fmaf(x4.x, Wc[4 * kq + 0], acc[i]);
            acc[i] = fmaf(x4.y, Wc[4 * kq + 1], acc[i]);
            acc[i] = fmaf(x4.z, Wc[4 * kq + 2], acc[i]);
            acc[i] = fmaf(x4.w, Wc[4 * kq + 3], acc[i]);
        }
    }
#pragma unroll
    for (int i = 0; i < 16; i++) {
        int r = r0 + rb + i;
        if (r < NN) H[(size_t)r * F + c] = acc[i];
    }

    // fused dots: reuse Xs as the H tile
    __syncthreads();
#pragma unroll
    for (int i = 0; i < 16; i++) Xs[(rb + i) * 64 + c] = acc[i];
    __syncthreads();

    int wid = tid >> 5, lane = tid & 31;
    float a0 = avs[lane], a1 = avs[32 + lane];
    float d0 = avd[lane], d1 = avd[32 + lane];
#pragma unroll
    for (int rr = 0; rr < 8; rr++) {
        int r = wid * 8 + rr;
        float h0 = Xs[r * 64 + lane];
        float h1 = Xs[r * 64 + 32 + lane];
        float s  = h0 * a0 + h1 * a1;
        float dd = h0 * d0 + h1 * d1;
#pragma unroll
        for (int o = 16; o; o >>= 1) {
            s  += __shfl_xor_sync(0xffffffffu, s,  o);
            dd += __shfl_xor_sync(0xffffffffu, dd, o);
        }
        int gr = r0 + r;
        if (lane == 0 && gr < NN) {
            ((float*)g_as2)[2 * gr + enc] = s;
            ((float*)g_ad2)[2 * gr + enc] = dd;
        }
    }
}

// ---------------- single-pass dual-encoder GAT aggregation ----------------
__global__ void __launch_bounds__(256) agg2_kernel(const float* __restrict__ bo,
                                                   const float* __restrict__ bt) {
    int d = (blockIdx.x * blockDim.x + threadIdx.x) >> 5;
    int lane = threadIdx.x & 31;
    if (d >= NN) return;

    int s0 = g_rowptr[d];
    int s1 = g_rowptr[d + 1];
    float2 adv = g_ad2[d];
    float2 asv = g_as2[d];
    float e0s = lrelu(asv.x + adv.x);
    float e1s = lrelu(asv.y + adv.y);
    float m0 = e0s, m1 = e1s;     // running maxes; self weight starts at 1

    const float2* h0 = (const float2*)g_h[0];
    const float2* h1 = (const float2*)g_h[1];
    float2 hd0 = h0[(size_t)d * 32 + lane];
    float2 hd1 = h1[(size_t)d * 32 + lane];
    float acc0x = hd0.x, acc0y = hd0.y;      // self message, weight exp(e_self - m) = 1
    float acc1x = hd1.x, acc1y = hd1.y;
    float den0 = (lane == 0) ? 1.f : 0.f;
    float den1 = den0;

    for (int base = s0; base < s1; base += 32) {
        int k = base + lane;
        bool valid = k < s1;
        int s = valid ? g_col[k] : 0;
        float e0 = -1e30f, e1 = -1e30f;
        if (valid) {
            float2 a = g_as2[s];
            e0 = lrelu(a.x + adv.x);
            e1 = lrelu(a.y + adv.y);
        }
        // warp-wide chunk maxes
        float c0 = e0, c1 = e1;
#pragma unroll
        for (int o = 16; o; o >>= 1) {
            c0 = fmaxf(c0, __shfl_xor_sync(0xffffffffu, c0, o));
            c1 = fmaxf(c1, __shfl_xor_sync(0xffffffffu, c1, o));
        }
        if (c0 > m0) { float sc = __expf(m0 - c0); acc0x *= sc; acc0y *= sc; den0 *= sc; m0 = c0; }
        if (c1 > m1) { float sc = __expf(m1 - c1); acc1x *= sc; acc1y *= sc; den1 *= sc; m1 = c1; }

        float w0 = valid ? __expf(e0 - m0) : 0.f;
        float w1 = valid ? __expf(e1 - m1) : 0.f;
        den0 += w0;
        den1 += w1;

        int cnt = min(32, s1 - base);
        for (int j = 0; j < cnt; j++) {
            int   sj  = __shfl_sync(0xffffffffu, s,  j);
            float w0j = __shfl_sync(0xffffffffu, w0, j);
            float w1j = __shfl_sync(0xffffffffu, w1, j);
            float2 v0 = h0[(size_t)sj * 32 + lane];
            float2 v1 = h1[(size_t)sj * 32 + lane];
            acc0x = fmaf(w0j, v0.x, acc0x);
            acc0y = fmaf(w0j, v0.y, acc0y);
            acc1x = fmaf(w1j, v1.x, acc1x);
            acc1y = fmaf(w1j, v1.y, acc1y);
        }
    }
#pragma unroll
    for (int o = 16; o; o >>= 1) {
        den0 += __shfl_xor_sync(0xffffffffu, den0, o);
        den1 += __shfl_xor_sync(0xffffffffu, den1, o);
    }
    float inv0 = 1.f / den0;
    float inv1 = 1.f / den1;

    float2 o0, o1;
    o0.x = acc0x * inv0 + bo[2 * lane];
    o0.y = acc0y * inv0 + bo[2 * lane + 1];
    o1.x = acc1x * inv1 + bt[2 * lane];
    o1.y = acc1y * inv1 + bt[2 * lane + 1];
    ((float2*)g_x[0])[(size_t)d * 32 + lane] = o0;
    ((float2*)g_x[1])[(size_t)d * 32 + lane] = o1;
}

// ---------------- predictor + output assembly ----------------
__global__ void __launch_bounds__(256) final_kernel(const float* __restrict__ pW,
                                                    const float* __restrict__ pb,
                                                    const int* __restrict__ user,
                                                    const int* __restrict__ item,
                                                    float* __restrict__ out) {
    __shared__ float Ws[64 * 65];
    __shared__ float rows[4 * 64];
    int tid = threadIdx.x;
    bool isU = blockIdx.x < (Q / 4);
    int qb = (isU ? blockIdx.x : blockIdx.x - (Q / 4)) * 4;

    for (int i = tid; i < 4096; i += 256) Ws[(i >> 6) * 65 + (i & 63)] = pW[i];

    int qr = tid >> 6, c = tid & 63;
    int q = qb + qr;
    int node = isU ? user[q] : (NUSER + item[q]);
    rows[qr * 64 + c] = g_x[0][(size_t)node * F + c];
    __syncthreads();

    float acc = pb[c];
#pragma unroll
    for (int k = 0; k < 64; k++) acc = fmaf(rows[qr * 64 + k], Ws[c * 65 + k], acc);

    size_t base = isU ? 0 : (size_t)2 * Q * F;
    out[base + (size_t)q * F + c] = acc;                                  // predicted
    out[base + (size_t)Q * F + (size_t)q * F + c] = g_x[1][(size_t)node * F + c];  // target
}

// ---------------- host ----------------
extern "C" void kernel_launch(void* const* d_in, const int* in_sizes, int n_in,
                              void* d_out, int out_size) {
    const float *uembo, *iembo, *Wo, *aso, *ado, *bo;
    const float *uembt, *iembt, *Wt, *ast, *adt, *bt;
    const float *pW, *pb;
    const int *user, *item, *ei;

    if (in_sizes[0] == Q) {  // setup_inputs dict order
        user  = (const int*)d_in[0];
        item  = (const int*)d_in[1];
        ei    = (const int*)d_in[2];
        uembo = (const float*)d_in[3];  iembo = (const float*)d_in[4];
        Wo    = (const float*)d_in[5];
        aso   = (const float*)d_in[6];  ado   = (const float*)d_in[7];  bo = (const float*)d_in[8];
        uembt = (const float*)d_in[9];  iembt = (const float*)d_in[10];
        Wt    = (const float*)d_in[11];
        ast   = (const float*)d_in[12]; adt   = (const float*)d_in[13]; bt = (const float*)d_in[14];
        pW    = (const float*)d_in[15]; pb    = (const float*)d_in[16];
    } else {                 // reference signature order
        uembo = (const float*)d_in[0];  iembo = (const float*)d_in[1];
        Wo    = (const float*)d_in[2];
        aso   = (const float*)d_in[3];  ado   = (const float*)d_in[4];  bo = (const float*)d_in[5];
        uembt = (const float*)d_in[6];  iembt = (const float*)d_in[7];
        Wt    = (const float*)d_in[8];
        ast   = (const float*)d_in[9];  adt   = (const float*)d_in[10]; bt = (const float*)d_in[11];
        pW    = (const float*)d_in[12]; pb    = (const float*)d_in[13];
        user  = (const int*)d_in[14];
        item  = (const int*)d_in[15];
        ei    = (const int*)d_in[16];
    }
    float* out = (float*)d_out;

    zero_counts_kernel<<<(NN + 255) / 256, 256>>>();
    hist_kernel<<<EE / 256, 256>>>(ei);
    scan_kernel<<<1, 1024>>>();
    scatter_kernel<<<EE / 256, 256>>>(ei);

    concat2_kernel<<<(2 * NN * (F / 4) + 255) / 256, 256>>>(
        (const float4*)uembo, (const float4*)iembo,
        (const float4*)uembt, (const float4*)iembt);

    const int GEMM_BLOCKS = (NN + 63) / 64;  // 2344
    const int WARP_BLOCKS = NN / 8;          // 18750

    for (int l = 0; l < 3; l++) {
        dim3 gg(GEMM_BLOCKS, 2);
        gemm_dots_kernel<<<gg, 256>>>(Wo + (size_t)l * F * F, Wt + (size_t)l * F * F,
                                      aso + l * F, ado + l * F, ast + l * F, adt + l * F);
        agg2_kernel<<<WARP_BLOCKS, 256>>>(bo + l * F, bt + l * F);
    }

    final_kernel<<<2 * (Q / 4), 256>>>(pW, pb, user, item, out);
}